// round 3
// baseline (speedup 1.0000x reference)
#include <cuda_runtime.h>

// BiasedFeatureDropout: out = x * 1.25 * (threefry_bits(i) < T(channel))
// Bit-exact JAX partitionable threefry-2x32, keys (0,1), counter hi=0.
//
// Round-3 build: plain C++ rounds (ptxas-friendly), 12/19 rounds use a
// mul.wide.u32 rotate (fma pipe) + fused LOP3 (a|b)^c, x0 key injections
// folded into 3-input IADD3 round adds, and NO register cap so ptxas can
// interleave the 8 independent hash streams (kills short-scoreboard
// bubbles that capped issue at 76%).

static constexpr unsigned KS2      = 0x1BD11BDBu;   // 0 ^ 1 ^ 0x1BD11BDA
static constexpr unsigned HW       = 56u * 56u;     // 3136, divisible by 8
static constexpr unsigned THR_BIAS = 858993664u;    // keep=0.2f
static constexpr unsigned THR_REG  = 3435974144u;   // keep=0.8f

struct Pows {                      // runtime-opaque 1u<<r values
    unsigned p6, p13, p15, p16, p17, p24, p26, p29;
};

// classic round: IADD3/IMAD add + SHF rotate + LOP3 xor
#define RC(rr)       { x0 += x1; x1 = __funnelshift_l(x1, x1, (rr)) ^ x0; }
#define RCI(rr, a)   { x0 += x1 + (a); x1 = __funnelshift_l(x1, x1, (rr)) ^ x0; }
// wide round: add + IMAD.WIDE rotate + LOP3 (lo|hi)^x0
#define RW(pp)       { x0 += x1;                                            \
                       unsigned long long t = (unsigned long long)x1 * (pp);\
                       x1 = ((unsigned)t | (unsigned)(t >> 32)) ^ x0; }
#define RWI(pp, a)   { x0 += x1 + (a);                                      \
                       unsigned long long t = (unsigned long long)x1 * (pp);\
                       x1 = ((unsigned)t | (unsigned)(t >> 32)) ^ x0; }

__device__ __forceinline__ unsigned threefry_bits(unsigned ctr, const Pows& P) {
    unsigned x0, x1;
    x1 = ctr + 1u;                       // x1 = ctr + ks1
    // group 0 (13,15,26,6); x0 = 0 + x1 folds round 1's add
    x0 = x1;
    x1 = __funnelshift_l(x1, x1, 13) ^ x0;
    RC(15) RW(P.p26) RW(P.p6)
    x1 += KS2 + 1u;                      // inj1: x1 += ks2 + 1
    // group 1 (17,29,16,24); x0 inj (+1) folded
    RWI(P.p17, 1u) RW(P.p29) RC(16) RW(P.p24)
    x1 += 2u;                            // inj2: x1 += ks0 + 2
    // group 2 (13,15,26,6); x0 inj (+KS2) folded
    RWI(P.p13, KS2) RC(15) RW(P.p26) RC(6)
    x1 += 4u;                            // inj3: x1 += ks1 + 3
    // group 3 (17,29,16,24); x0 inj (+0) free
    RW(P.p17) RW(P.p29) RC(16) RW(P.p24)
    x1 += KS2 + 4u;                      // inj4: x1 += ks2 + 4
    // group 4 (13,15,26,6); x0 inj (+1) folded
    RWI(P.p13, 1u) RC(15) RW(P.p26) RC(6)
    // final injection + fold: (x0 + ks2) ^ (x1 + ks0 + 5)
    return (x0 + KS2) ^ (x1 + 5u);
}

__global__ __launch_bounds__(256)
void biased_dropout_kernel(const float4* __restrict__ x,
                           float4* __restrict__ y,
                           unsigned one,            // always 1, opaque to ptxas
                           unsigned n_thr) {
    unsigned t = blockIdx.x * blockDim.x + threadIdx.x;
    if (t >= n_thr) return;

    unsigned base = t * 8u;
    unsigned ch  = (base / HW) & 255u;               // HW % 8 == 0
    unsigned thr = (ch < 32u) ? THR_BIAS : THR_REG;

    Pows P;
    P.p6  = one << 6;  P.p13 = one << 13; P.p15 = one << 15; P.p16 = one << 16;
    P.p17 = one << 17; P.p24 = one << 24; P.p26 = one << 26; P.p29 = one << 29;

    float4 v0 = x[2u * t];
    float4 v1 = x[2u * t + 1u];

    unsigned b[8];
#pragma unroll
    for (int i = 0; i < 8; i++)
        b[i] = threefry_bits(base + (unsigned)i, P);

    float4 o0, o1;
    o0.x = (b[0] < thr) ? v0.x * 1.25f : 0.0f;
    o0.y = (b[1] < thr) ? v0.y * 1.25f : 0.0f;
    o0.z = (b[2] < thr) ? v0.z * 1.25f : 0.0f;
    o0.w = (b[3] < thr) ? v0.w * 1.25f : 0.0f;
    o1.x = (b[4] < thr) ? v1.x * 1.25f : 0.0f;
    o1.y = (b[5] < thr) ? v1.y * 1.25f : 0.0f;
    o1.z = (b[6] < thr) ? v1.z * 1.25f : 0.0f;
    o1.w = (b[7] < thr) ? v1.w * 1.25f : 0.0f;

    y[2u * t]      = o0;
    y[2u * t + 1u] = o1;
}

extern "C" void kernel_launch(void* const* d_in, const int* in_sizes, int n_in,
                              void* d_out, int out_size) {
    (void)n_in; (void)out_size;
    const float4* x = (const float4*)d_in[0];
    float4* y = (float4*)d_out;
    unsigned n = (unsigned)in_sizes[0];          // 51,380,224
    unsigned n_thr = n / 8u;                     // 6,422,528 (exact)
    unsigned blocks = (n_thr + 255u) / 256u;     // 25,088
    biased_dropout_kernel<<<blocks, 256>>>(x, y, 1u, n_thr);
}